// round 16
// baseline (speedup 1.0000x reference)
#include <cuda_runtime.h>
#include <cuda_bf16.h>
#include <cstdint>

// Problem constants
#define BATCH   8
#define SEQ     1024
#define CH      1024
#define HEADS   16
#define HDIM    64
#define M0      (BATCH*SEQ)      // 8192 rows
#define BH      (BATCH*HEADS)    // 128 (b,h) pairs

// ---------------- scratch (static device memory: allocation-free rule) ----
__device__ float g_qkv[(size_t)M0 * 3 * CH];          // 96 MB  [B*N, 3C]
__device__ float g_att[(size_t)M0 * CH];              // 32 MB  [B*N, C]

// ---------------- helpers --------------------------------------------------
__device__ __forceinline__ uint32_t pack_bf16(__nv_bfloat16 a, __nv_bfloat16 b) {
    return (uint32_t)__bfloat16_as_ushort(a) | ((uint32_t)__bfloat16_as_ushort(b) << 16);
}

__device__ __forceinline__ void split2(float f, __nv_bfloat16& h, __nv_bfloat16& l) {
    h = __float2bfloat16(f);
    l = __float2bfloat16(f - __bfloat162float(h));
}

__device__ __forceinline__ void cvt_store(__nv_bfloat16* ph, __nv_bfloat16* pl, float4 v) {
    __nv_bfloat16 h0,h1,h2,h3,l0,l1,l2,l3;
    split2(v.x,h0,l0); split2(v.y,h1,l1); split2(v.z,h2,l2); split2(v.w,h3,l3);
    *reinterpret_cast<uint2*>(ph) = make_uint2(pack_bf16(h0,h1), pack_bf16(h2,h3));
    *reinterpret_cast<uint2*>(pl) = make_uint2(pack_bf16(l0,l1), pack_bf16(l2,l3));
}

__device__ __forceinline__ void mma_bf16_16816(float c[4], const uint32_t a[4],
                                               const uint32_t b[2]) {
    asm("mma.sync.aligned.m16n8k16.row.col.f32.bf16.bf16.f32 "
        "{%0,%1,%2,%3}, {%4,%5,%6,%7}, {%8,%9}, {%0,%1,%2,%3};\n"
        : "+f"(c[0]), "+f"(c[1]), "+f"(c[2]), "+f"(c[3])
        : "r"(a[0]), "r"(a[1]), "r"(a[2]), "r"(a[3]),
          "r"(b[0]), "r"(b[1]));
}

// ---------------------------------------------------------------------------
// Pipelined bf16x3 GEMM: C[m][n] = sum_k A[m][k]*B[n][k] (+bias[n])
//   BM=BN=128, BK=32, **512 threads / 16 warps** (4x4 warp grid, 32x32 warp
//   tile) to double resident warps vs R13 (occupancy was the binder).
//   Double-buffered smem stages + register prefetch of the next gmem tile.
//   Dynamic smem: 2 stages x (Ah+Al+Bh+Bl @ 128x40 bf16) = 81920 B
// ---------------------------------------------------------------------------
template<bool HAS_BIAS>
__global__ void __launch_bounds__(512, 1)
gemm_bf16x3(const float* __restrict__ A, int ldA,
            const float* __restrict__ B, int ldB,
            float*       __restrict__ C, int ldC,
            const float* __restrict__ bias, int K)
{
    constexpr int BM = 128, BKP = 40;
    extern __shared__ char smem_raw[];

    const int tid  = threadIdx.x;
    const int warp = tid >> 5;
    const int lane = tid & 31;
    const int wm   = warp >> 2;        // 0..3  (rows of warp grid)
    const int wn   = warp & 3;         // 0..3  (cols of warp grid)
    const int g    = lane >> 2;
    const int t4   = lane & 3;
    const int n0   = blockIdx.x * 128;

    const float* Ab = A + (size_t)blockIdx.y * 128 * ldA;
    const float* Bb = B + (size_t)n0 * ldB;
    float*       Cb = C + (size_t)blockIdx.y * 128 * ldC + n0;

    float acc[2][4][4];
    #pragma unroll
    for (int mt = 0; mt < 2; mt++)
        #pragma unroll
        for (int nt = 0; nt < 4; nt++)
            #pragma unroll
            for (int i = 0; i < 4; i++) acc[mt][nt][i] = 0.f;

    float4 ra[2], rb[2];

    auto load_regs = [&](int k0) {
        #pragma unroll
        for (int p = 0; p < 2; p++) {
            int idx = p * 512 + tid;
            int row = idx >> 3;            // 8 float4 per row (BK=32)
            int cc  = (idx & 7) << 2;
            ra[p] = *reinterpret_cast<const float4*>(Ab + (size_t)row * ldA + k0 + cc);
            rb[p] = *reinterpret_cast<const float4*>(Bb + (size_t)row * ldB + k0 + cc);
        }
    };
    auto store_smem = [&](int s) {
        __nv_bfloat16* ah = (__nv_bfloat16*)(smem_raw + s * 40960);
        __nv_bfloat16* al = ah + BM * BKP;
        __nv_bfloat16* bh = ah + 2 * BM * BKP;
        __nv_bfloat16* bl = ah + 3 * BM * BKP;
        #pragma unroll
        for (int p = 0; p < 2; p++) {
            int idx = p * 512 + tid;
            int row = idx >> 3;
            int cc  = (idx & 7) << 2;
            cvt_store(ah + row * BKP + cc, al + row * BKP + cc, ra[p]);
            cvt_store(bh + row * BKP + cc, bl + row * BKP + cc, rb[p]);
        }
    };

    load_regs(0);
    store_smem(0);
    __syncthreads();

    const int nk = K / 32;
    for (int it = 0; it < nk; it++) {
        const int cur = it & 1;
        if (it + 1 < nk) load_regs((it + 1) * 32);

        const __nv_bfloat16* ah = (const __nv_bfloat16*)(smem_raw + cur * 40960);
        const __nv_bfloat16* al = ah + BM * BKP;
        const __nv_bfloat16* bh = ah + 2 * BM * BKP;
        const __nv_bfloat16* bl = ah + 3 * BM * BKP;

        #pragma unroll
        for (int ks = 0; ks < 2; ks++) {
            const int kb = ks * 16 + (t4 << 1);
            uint32_t ahi[2][4], alo[2][4], bhi[4][2], blo[4][2];
            #pragma unroll
            for (int mt = 0; mt < 2; mt++) {
                const int r = wm * 32 + mt * 16 + g;
                ahi[mt][0] = *(const uint32_t*)(ah + r * BKP + kb);
                ahi[mt][1] = *(const uint32_t*)(ah + (r + 8) * BKP + kb);
                ahi[mt][2] = *(const uint32_t*)(ah + r * BKP + kb + 8);
                ahi[mt][3] = *(const uint32_t*)(ah + (r + 8) * BKP + kb + 8);
                alo[mt][0] = *(const uint32_t*)(al + r * BKP + kb);
                alo[mt][1] = *(const uint32_t*)(al + (r + 8) * BKP + kb);
                alo[mt][2] = *(const uint32_t*)(al + r * BKP + kb + 8);
                alo[mt][3] = *(const uint32_t*)(al + (r + 8) * BKP + kb + 8);
            }
            #pragma unroll
            for (int nt = 0; nt < 4; nt++) {
                const int n = wn * 32 + nt * 8 + g;
                bhi[nt][0] = *(const uint32_t*)(bh + n * BKP + kb);
                bhi[nt][1] = *(const uint32_t*)(bh + n * BKP + kb + 8);
                blo[nt][0] = *(const uint32_t*)(bl + n * BKP + kb);
                blo[nt][1] = *(const uint32_t*)(bl + n * BKP + kb + 8);
            }
            #pragma unroll
            for (int mt = 0; mt < 2; mt++)
                #pragma unroll
                for (int nt = 0; nt < 4; nt++) {
                    mma_bf16_16816(acc[mt][nt], ahi[mt], bhi[nt]);
                    mma_bf16_16816(acc[mt][nt], ahi[mt], blo[nt]);
                    mma_bf16_16816(acc[mt][nt], alo[mt], bhi[nt]);
                }
        }

        if (it + 1 < nk) store_smem(cur ^ 1);
        __syncthreads();
    }

    // epilogue
    #pragma unroll
    for (int mt = 0; mt < 2; mt++) {
        const int r = wm * 32 + mt * 16 + g;
        #pragma unroll
        for (int nt = 0; nt < 4; nt++) {
            const int c = wn * 32 + nt * 8 + (t4 << 1);
            float2 v0 = make_float2(acc[mt][nt][0], acc[mt][nt][1]);
            float2 v1 = make_float2(acc[mt][nt][2], acc[mt][nt][3]);
            if constexpr (HAS_BIAS) {
                float2 bb = *reinterpret_cast<const float2*>(bias + n0 + c);
                v0.x += bb.x; v0.y += bb.y; v1.x += bb.x; v1.y += bb.y;
            }
            *reinterpret_cast<float2*>(Cb + (size_t)r       * ldC + c) = v0;
            *reinterpret_cast<float2*>(Cb + (size_t)(r + 8) * ldC + c) = v1;
        }
    }
}

// ---------------------------------------------------------------------------
// Flash attention, bf16x3 (HMMA path) — unchanged from R13 (passing).
// One CTA = 128 Q rows of one (b,h). KV tiles of 64, double-buffered.
// Dynamic smem: Q 36864 + 2 stages x 36864 = 110592 B
// ---------------------------------------------------------------------------
__global__ void __launch_bounds__(256, 1)
flash_attn(const float* __restrict__ qkv, float* __restrict__ att)
{
    extern __shared__ char smem_raw[];
    __nv_bfloat16* Qh = (__nv_bfloat16*)smem_raw;        // [128][72]
    __nv_bfloat16* Ql = Qh + 128 * 72;

    const int tid  = threadIdx.x;
    const int warp = tid >> 5;
    const int lane = tid & 31;
    const int g    = lane >> 2;
    const int t4   = lane & 3;
    const int b    = blockIdx.x >> 4;
    const int h    = blockIdx.x & 15;
    const int q0   = blockIdx.y * 128;

    const float* Qg = qkv + (size_t)(b * SEQ + q0) * (3 * CH) + h * HDIM;
    const float* Kg = qkv + (size_t)b * SEQ * (3 * CH) + CH + h * HDIM;
    const float* Vg = Kg + CH;

    #pragma unroll
    for (int p = 0; p < 8; p++) {
        int idx = p * 256 + tid;
        int row = idx >> 4;
        int cc  = (idx & 15) << 2;
        float4 v = *reinterpret_cast<const float4*>(Qg + (size_t)row * (3 * CH) + cc);
        v.x *= 0.125f; v.y *= 0.125f; v.z *= 0.125f; v.w *= 0.125f;
        cvt_store(Qh + row * 72 + cc, Ql + row * 72 + cc, v);
    }

    float4 rk[4];
    float  rv[16];
    auto ldKV = [&](int kv0) {
        #pragma unroll
        for (int p = 0; p < 4; p++) {
            int idx = p * 256 + tid;
            {   int row = idx >> 4, cc = (idx & 15) << 2;
                rk[p] = *reinterpret_cast<const float4*>(Kg + (size_t)(kv0 + row) * (3 * CH) + cc); }
            {   int d = idx & 63, k4 = (idx >> 6) << 2;
                #pragma unroll
                for (int i = 0; i < 4; i++)
                    rv[p * 4 + i] = Vg[(size_t)(kv0 + k4 + i) * (3 * CH) + d]; }
        }
    };
    auto stKV = [&](int s) {
        __nv_bfloat16* Kh = (__nv_bfloat16*)(smem_raw + 36864 + s * 36864);
        __nv_bfloat16* Kl = Kh + 64 * 72;
        __nv_bfloat16* Vh = Kh + 2 * 64 * 72;
        __nv_bfloat16* Vl = Kh + 3 * 64 * 72;
        #pragma unroll
        for (int p = 0; p < 4; p++) {
            int idx = p * 256 + tid;
            {   int row = idx >> 4, cc = (idx & 15) << 2;
                cvt_store(Kh + row * 72 + cc, Kl + row * 72 + cc, rk[p]); }
            {   int d = idx & 63, k4 = (idx >> 6) << 2;
                __nv_bfloat16 hh[4], ll[4];
                #pragma unroll
                for (int i = 0; i < 4; i++) split2(rv[p * 4 + i], hh[i], ll[i]);
                *reinterpret_cast<uint2*>(Vh + d * 72 + k4) =
                    make_uint2(pack_bf16(hh[0], hh[1]), pack_bf16(hh[2], hh[3]));
                *reinterpret_cast<uint2*>(Vl + d * 72 + k4) =
                    make_uint2(pack_bf16(ll[0], ll[1]), pack_bf16(ll[2], ll[3])); }
        }
    };

    const int r = warp * 16 + g;
    float m0 = -1e30f, m1 = -1e30f, l0 = 0.f, l1 = 0.f;
    float o[8][4];
    #pragma unroll
    for (int d8 = 0; d8 < 8; d8++)
        #pragma unroll
        for (int i = 0; i < 4; i++) o[d8][i] = 0.f;

    ldKV(0);
    stKV(0);
    __syncthreads();

    for (int j = 0; j < 16; j++) {
        const int cur = j & 1;
        if (j < 15) ldKV((j + 1) * 64);

        const __nv_bfloat16* Kh = (const __nv_bfloat16*)(smem_raw + 36864 + cur * 36864);
        const __nv_bfloat16* Kl = Kh + 64 * 72;
        const __nv_bfloat16* Vh = Kh + 2 * 64 * 72;
        const __nv_bfloat16* Vl = Kh + 3 * 64 * 72;

        float s_[8][4];
        #pragma unroll
        for (int nt = 0; nt < 8; nt++)
            #pragma unroll
            for (int i = 0; i < 4; i++) s_[nt][i] = 0.f;

        #pragma unroll
        for (int ks = 0; ks < 4; ks++) {
            const int kb = ks * 16 + (t4 << 1);
            uint32_t ah[4], al[4];
            ah[0] = *(const uint32_t*)(Qh + r * 72 + kb);
            ah[1] = *(const uint32_t*)(Qh + (r + 8) * 72 + kb);
            ah[2] = *(const uint32_t*)(Qh + r * 72 + kb + 8);
            ah[3] = *(const uint32_t*)(Qh + (r + 8) * 72 + kb + 8);
            al[0] = *(const uint32_t*)(Ql + r * 72 + kb);
            al[1] = *(const uint32_t*)(Ql + (r + 8) * 72 + kb);
            al[2] = *(const uint32_t*)(Ql + r * 72 + kb + 8);
            al[3] = *(const uint32_t*)(Ql + (r + 8) * 72 + kb + 8);
            #pragma unroll
            for (int nt = 0; nt < 8; nt++) {
                const int n = nt * 8 + g;
                uint32_t bh2[2] = { *(const uint32_t*)(Kh + n * 72 + kb),
                                    *(const uint32_t*)(Kh + n * 72 + kb + 8) };
                uint32_t bl2[2] = { *(const uint32_t*)(Kl + n * 72 + kb),
                                    *(const uint32_t*)(Kl + n * 72 + kb + 8) };
                mma_bf16_16816(s_[nt], ah, bh2);
                mma_bf16_16816(s_[nt], ah, bl2);
                mma_bf16_16816(s_[nt], al, bh2);
            }
        }

        float mx0 = -1e30f, mx1 = -1e30f;
        #pragma unroll
        for (int nt = 0; nt < 8; nt++) {
            mx0 = fmaxf(mx0, fmaxf(s_[nt][0], s_[nt][1]));
            mx1 = fmaxf(mx1, fmaxf(s_[nt][2], s_[nt][3]));
        }
        mx0 = fmaxf(mx0, __shfl_xor_sync(0xffffffffu, mx0, 1));
        mx0 = fmaxf(mx0, __shfl_xor_sync(0xffffffffu, mx0, 2));
        mx1 = fmaxf(mx1, __shfl_xor_sync(0xffffffffu, mx1, 1));
        mx1 = fmaxf(mx1, __shfl_xor_sync(0xffffffffu, mx1, 2));

        const float nm0 = fmaxf(m0, mx0), nm1 = fmaxf(m1, mx1);
        const float f0 = __expf(m0 - nm0), f1 = __expf(m1 - nm1);
        float sm0 = 0.f, sm1 = 0.f;
        #pragma unroll
        for (int nt = 0; nt < 8; nt++) {
            s_[nt][0] = __expf(s_[nt][0] - nm0);
            s_[nt][1] = __expf(s_[nt][1] - nm0);
            s_[nt][2] = __expf(s_[nt][2] - nm1);
            s_[nt][3] = __expf(s_[nt][3] - nm1);
            sm0 += s_[nt][0] + s_[nt][1];
            sm1 += s_[nt][2] + s_[nt][3];
        }
        sm0 += __shfl_xor_sync(0xffffffffu, sm0, 1);
        sm0 += __shfl_xor_sync(0xffffffffu, sm0, 2);
        sm1 += __shfl_xor_sync(0xffffffffu, sm1, 1);
        sm1 += __shfl_xor_sync(0xffffffffu, sm1, 2);

        l0 = l0 * f0 + sm0;  l1 = l1 * f1 + sm1;
        m0 = nm0;            m1 = nm1;

        #pragma unroll
        for (int d8 = 0; d8 < 8; d8++) {
            o[d8][0] *= f0; o[d8][1] *= f0;
            o[d8][2] *= f1; o[d8][3] *= f1;
        }

        #pragma unroll
        for (int ks = 0; ks < 4; ks++) {
            uint32_t ah[4], al[4];
            {
                __nv_bfloat16 ph[4], pl[4];
                split2(s_[2*ks][0], ph[0], pl[0]); split2(s_[2*ks][1], ph[1], pl[1]);
                split2(s_[2*ks][2], ph[2], pl[2]); split2(s_[2*ks][3], ph[3], pl[3]);
                ah[0] = pack_bf16(ph[0], ph[1]); ah[1] = pack_bf16(ph[2], ph[3]);
                al[0] = pack_bf16(pl[0], pl[1]); al[1] = pack_bf16(pl[2], pl[3]);
                split2(s_[2*ks+1][0], ph[0], pl[0]); split2(s_[2*ks+1][1], ph[1], pl[1]);
                split2(s_[2*ks+1][2], ph[2], pl[2]); split2(s_[2*ks+1][3], ph[3], pl[3]);
                ah[2] = pack_bf16(ph[0], ph[1]); ah[3] = pack_bf16(ph[2], ph[3]);
                al[2] = pack_bf16(pl[0], pl[1]); al[3] = pack_bf16(pl[2], pl[3]);
            }
            const int kb = ks * 16 + (t4 << 1);
            #pragma unroll
            for (int d8 = 0; d8 < 8; d8++) {
                const int n = d8 * 8 + g;
                uint32_t bh2[2] = { *(const uint32_t*)(Vh + n * 72 + kb),
                                    *(const uint32_t*)(Vh + n * 72 + kb + 8) };
                uint32_t bl2[2] = { *(const uint32_t*)(Vl + n * 72 + kb),
                                    *(const uint32_t*)(Vl + n * 72 + kb + 8) };
                mma_bf16_16816(o[d8], ah, bh2);
                mma_bf16_16816(o[d8], ah, bl2);
                mma_bf16_16816(o[d8], al, bh2);
            }
        }

        if (j < 15) stKV(cur ^ 1);
        __syncthreads();
    }

    const float i0 = 1.f / l0, i1 = 1.f / l1;
    float* O0 = att + (size_t)(b * SEQ + q0 + r) * CH + h * HDIM;
    float* O1 = O0 + (size_t)8 * CH;
    #pragma unroll
    for (int d8 = 0; d8 < 8; d8++) {
        const int c = d8 * 8 + (t4 << 1);
        *reinterpret_cast<float2*>(O0 + c) = make_float2(o[d8][0] * i0, o[d8][1] * i0);
        *reinterpret_cast<float2*>(O1 + c) = make_float2(o[d8][2] * i1, o[d8][3] * i1);
    }
}

// ---------------------------------------------------------------------------
extern "C" void kernel_launch(void* const* d_in, const int* in_sizes, int n_in,
                              void* d_out, int out_size)
{
    (void)in_sizes; (void)n_in; (void)out_size;
    const float* x     = (const float*)d_in[0];   // [8, 1024, 1024]
    const float* wqkv  = (const float*)d_in[1];   // [3072, 1024]
    const float* wproj = (const float*)d_in[2];   // [1024, 1024]
    const float* bproj = (const float*)d_in[3];   // [1024]
    float*       out   = (float*)d_out;           // [8, 1024, 1024]

    float *qkv, *att;
    cudaGetSymbolAddress((void**)&qkv, g_qkv);
    cudaGetSymbolAddress((void**)&att, g_att);

    cudaFuncSetAttribute(gemm_bf16x3<false>,
                         cudaFuncAttributeMaxDynamicSharedMemorySize, 81920);
    cudaFuncSetAttribute(gemm_bf16x3<true>,
                         cudaFuncAttributeMaxDynamicSharedMemorySize, 81920);
    cudaFuncSetAttribute(flash_attn,
                         cudaFuncAttributeMaxDynamicSharedMemorySize, 110592);

    // 1) QKV projection: [8192,1024] x [3072,1024]^T -> g_qkv [8192,3072]
    gemm_bf16x3<false><<<dim3(3 * CH / 128, M0 / 128), 512, 81920>>>(
        x, CH, wqkv, CH, qkv, 3 * CH, nullptr, CH);

    // 2) Fused flash attention -> g_att [8192,1024]
    flash_attn<<<dim3(BH, SEQ / 128), 256, 110592>>>(qkv, att);

    // 3) Output projection + bias
    gemm_bf16x3<true><<<dim3(CH / 128, M0 / 128), 512, 81920>>>(
        att, CH, wproj, CH, out, CH, bproj, CH);
}

// round 17
// speedup vs baseline: 1.5696x; 1.5696x over previous
#include <cuda_runtime.h>
#include <cuda_bf16.h>
#include <cstdint>

// Problem constants
#define BATCH   8
#define SEQ     1024
#define CH      1024
#define HEADS   16
#define HDIM    64
#define M0      (BATCH*SEQ)      // 8192 rows
#define BH      (BATCH*HEADS)    // 128 (b,h) pairs

// ---------------- scratch (static device memory: allocation-free rule) ----
__device__ float g_qkv[(size_t)M0 * 3 * CH];          // 96 MB  [B*N, 3C]
__device__ float g_att[(size_t)M0 * CH];              // 32 MB  [B*N, C]

// ---------------- helpers --------------------------------------------------
__device__ __forceinline__ uint32_t pack_bf16(__nv_bfloat16 a, __nv_bfloat16 b) {
    return (uint32_t)__bfloat16_as_ushort(a) | ((uint32_t)__bfloat16_as_ushort(b) << 16);
}

__device__ __forceinline__ void split2(float f, __nv_bfloat16& h, __nv_bfloat16& l) {
    h = __float2bfloat16(f);
    l = __float2bfloat16(f - __bfloat162float(h));
}

__device__ __forceinline__ void cvt_store(__nv_bfloat16* ph, __nv_bfloat16* pl, float4 v) {
    __nv_bfloat16 h0,h1,h2,h3,l0,l1,l2,l3;
    split2(v.x,h0,l0); split2(v.y,h1,l1); split2(v.z,h2,l2); split2(v.w,h3,l3);
    *reinterpret_cast<uint2*>(ph) = make_uint2(pack_bf16(h0,h1), pack_bf16(h2,h3));
    *reinterpret_cast<uint2*>(pl) = make_uint2(pack_bf16(l0,l1), pack_bf16(l2,l3));
}

__device__ __forceinline__ void mma_bf16_16816(float c[4], const uint32_t a[4],
                                               const uint32_t b[2]) {
    asm("mma.sync.aligned.m16n8k16.row.col.f32.bf16.bf16.f32 "
        "{%0,%1,%2,%3}, {%4,%5,%6,%7}, {%8,%9}, {%0,%1,%2,%3};\n"
        : "+f"(c[0]), "+f"(c[1]), "+f"(c[2]), "+f"(c[3])
        : "r"(a[0]), "r"(a[1]), "r"(a[2]), "r"(a[3]),
          "r"(b[0]), "r"(b[1]));
}

// ---------------------------------------------------------------------------
// Pipelined bf16x3 GEMM (R13 shape: 256 thr, 2x4 warps, 64x32 warp tile).
// KEY CHANGE vs R13: the 3 split-terms are issued term-outermost so
// consecutive HMMAs never share an accumulator (RAW distance 1 -> 16).
// Dynamic smem: 2 stages x (Ah+Al+Bh+Bl @ 128x40 bf16) = 81920 B
// ---------------------------------------------------------------------------
template<bool HAS_BIAS>
__global__ void __launch_bounds__(256, 1)
gemm_bf16x3(const float* __restrict__ A, int ldA,
            const float* __restrict__ B, int ldB,
            float*       __restrict__ C, int ldC,
            const float* __restrict__ bias, int K)
{
    constexpr int BM = 128, BKP = 40;
    extern __shared__ char smem_raw[];

    const int tid  = threadIdx.x;
    const int warp = tid >> 5;
    const int lane = tid & 31;
    const int wm   = warp >> 2;        // WARPS_M = 2
    const int wn   = warp & 3;         // WARPS_N = 4
    const int g    = lane >> 2;
    const int t4   = lane & 3;
    const int n0   = blockIdx.x * 128;

    const float* Ab = A + (size_t)blockIdx.y * 128 * ldA;
    const float* Bb = B + (size_t)n0 * ldB;
    float*       Cb = C + (size_t)blockIdx.y * 128 * ldC + n0;

    float acc[4][4][4];
    #pragma unroll
    for (int mt = 0; mt < 4; mt++)
        #pragma unroll
        for (int nt = 0; nt < 4; nt++)
            #pragma unroll
            for (int i = 0; i < 4; i++) acc[mt][nt][i] = 0.f;

    float4 ra[4], rb[4];

    auto load_regs = [&](int k0) {
        #pragma unroll
        for (int p = 0; p < 4; p++) {
            int idx = p * 256 + tid;
            int row = idx >> 3;
            int cc  = (idx & 7) << 2;
            ra[p] = *reinterpret_cast<const float4*>(Ab + (size_t)row * ldA + k0 + cc);
            rb[p] = *reinterpret_cast<const float4*>(Bb + (size_t)row * ldB + k0 + cc);
        }
    };
    auto store_smem = [&](int s) {
        __nv_bfloat16* ah = (__nv_bfloat16*)(smem_raw + s * 40960);
        __nv_bfloat16* al = ah + BM * BKP;
        __nv_bfloat16* bh = ah + 2 * BM * BKP;
        __nv_bfloat16* bl = ah + 3 * BM * BKP;
        #pragma unroll
        for (int p = 0; p < 4; p++) {
            int idx = p * 256 + tid;
            int row = idx >> 3;
            int cc  = (idx & 7) << 2;
            cvt_store(ah + row * BKP + cc, al + row * BKP + cc, ra[p]);
            cvt_store(bh + row * BKP + cc, bl + row * BKP + cc, rb[p]);
        }
    };

    load_regs(0);
    store_smem(0);
    __syncthreads();

    const int nk = K / 32;
    for (int it = 0; it < nk; it++) {
        const int cur = it & 1;
        if (it + 1 < nk) load_regs((it + 1) * 32);

        const __nv_bfloat16* ah = (const __nv_bfloat16*)(smem_raw + cur * 40960);
        const __nv_bfloat16* al = ah + BM * BKP;
        const __nv_bfloat16* bh = ah + 2 * BM * BKP;
        const __nv_bfloat16* bl = ah + 3 * BM * BKP;

        #pragma unroll
        for (int ks = 0; ks < 2; ks++) {
            const int kb = ks * 16 + (t4 << 1);
            uint32_t ahi[4][4], alo[4][4], bhi[4][2], blo[4][2];
            #pragma unroll
            for (int mt = 0; mt < 4; mt++) {
                const int r = wm * 64 + mt * 16 + g;
                ahi[mt][0] = *(const uint32_t*)(ah + r * BKP + kb);
                ahi[mt][1] = *(const uint32_t*)(ah + (r + 8) * BKP + kb);
                ahi[mt][2] = *(const uint32_t*)(ah + r * BKP + kb + 8);
                ahi[mt][3] = *(const uint32_t*)(ah + (r + 8) * BKP + kb + 8);
                alo[mt][0] = *(const uint32_t*)(al + r * BKP + kb);
                alo[mt][1] = *(const uint32_t*)(al + (r + 8) * BKP + kb);
                alo[mt][2] = *(const uint32_t*)(al + r * BKP + kb + 8);
                alo[mt][3] = *(const uint32_t*)(al + (r + 8) * BKP + kb + 8);
            }
            #pragma unroll
            for (int nt = 0; nt < 4; nt++) {
                const int n = wn * 32 + nt * 8 + g;
                bhi[nt][0] = *(const uint32_t*)(bh + n * BKP + kb);
                bhi[nt][1] = *(const uint32_t*)(bh + n * BKP + kb + 8);
                blo[nt][0] = *(const uint32_t*)(bl + n * BKP + kb);
                blo[nt][1] = *(const uint32_t*)(bl + n * BKP + kb + 8);
            }
            // term-outermost: 16 independent accumulators between reuses
            #pragma unroll
            for (int mt = 0; mt < 4; mt++)
                #pragma unroll
                for (int nt = 0; nt < 4; nt++)
                    mma_bf16_16816(acc[mt][nt], ahi[mt], bhi[nt]);
            #pragma unroll
            for (int mt = 0; mt < 4; mt++)
                #pragma unroll
                for (int nt = 0; nt < 4; nt++)
                    mma_bf16_16816(acc[mt][nt], ahi[mt], blo[nt]);
            #pragma unroll
            for (int mt = 0; mt < 4; mt++)
                #pragma unroll
                for (int nt = 0; nt < 4; nt++)
                    mma_bf16_16816(acc[mt][nt], alo[mt], bhi[nt]);
        }

        if (it + 1 < nk) store_smem(cur ^ 1);
        __syncthreads();
    }

    // epilogue
    #pragma unroll
    for (int mt = 0; mt < 4; mt++) {
        const int r = wm * 64 + mt * 16 + g;
        #pragma unroll
        for (int nt = 0; nt < 4; nt++) {
            const int c = wn * 32 + nt * 8 + (t4 << 1);
            float2 v0 = make_float2(acc[mt][nt][0], acc[mt][nt][1]);
            float2 v1 = make_float2(acc[mt][nt][2], acc[mt][nt][3]);
            if constexpr (HAS_BIAS) {
                float2 bb = *reinterpret_cast<const float2*>(bias + n0 + c);
                v0.x += bb.x; v0.y += bb.y; v1.x += bb.x; v1.y += bb.y;
            }
            *reinterpret_cast<float2*>(Cb + (size_t)r       * ldC + c) = v0;
            *reinterpret_cast<float2*>(Cb + (size_t)(r + 8) * ldC + c) = v1;
        }
    }
}

// ---------------------------------------------------------------------------
// Flash attention, bf16x3. Same structure as R13, but S and PV MMAs are
// issued term-outermost in groups of 4 tiles (RAW distance 1 -> 4).
// Dynamic smem: Q 36864 + 2 stages x 36864 = 110592 B
// ---------------------------------------------------------------------------
__global__ void __launch_bounds__(256, 1)
flash_attn(const float* __restrict__ qkv, float* __restrict__ att)
{
    extern __shared__ char smem_raw[];
    __nv_bfloat16* Qh = (__nv_bfloat16*)smem_raw;        // [128][72]
    __nv_bfloat16* Ql = Qh + 128 * 72;

    const int tid  = threadIdx.x;
    const int warp = tid >> 5;
    const int lane = tid & 31;
    const int g    = lane >> 2;
    const int t4   = lane & 3;
    const int b    = blockIdx.x >> 4;
    const int h    = blockIdx.x & 15;
    const int q0   = blockIdx.y * 128;

    const float* Qg = qkv + (size_t)(b * SEQ + q0) * (3 * CH) + h * HDIM;
    const float* Kg = qkv + (size_t)b * SEQ * (3 * CH) + CH + h * HDIM;
    const float* Vg = Kg + CH;

    #pragma unroll
    for (int p = 0; p < 8; p++) {
        int idx = p * 256 + tid;
        int row = idx >> 4;
        int cc  = (idx & 15) << 2;
        float4 v = *reinterpret_cast<const float4*>(Qg + (size_t)row * (3 * CH) + cc);
        v.x *= 0.125f; v.y *= 0.125f; v.z *= 0.125f; v.w *= 0.125f;
        cvt_store(Qh + row * 72 + cc, Ql + row * 72 + cc, v);
    }

    float4 rk[4];
    float  rv[16];
    auto ldKV = [&](int kv0) {
        #pragma unroll
        for (int p = 0; p < 4; p++) {
            int idx = p * 256 + tid;
            {   int row = idx >> 4, cc = (idx & 15) << 2;
                rk[p] = *reinterpret_cast<const float4*>(Kg + (size_t)(kv0 + row) * (3 * CH) + cc); }
            {   int d = idx & 63, k4 = (idx >> 6) << 2;
                #pragma unroll
                for (int i = 0; i < 4; i++)
                    rv[p * 4 + i] = Vg[(size_t)(kv0 + k4 + i) * (3 * CH) + d]; }
        }
    };
    auto stKV = [&](int s) {
        __nv_bfloat16* Kh = (__nv_bfloat16*)(smem_raw + 36864 + s * 36864);
        __nv_bfloat16* Kl = Kh + 64 * 72;
        __nv_bfloat16* Vh = Kh + 2 * 64 * 72;
        __nv_bfloat16* Vl = Kh + 3 * 64 * 72;
        #pragma unroll
        for (int p = 0; p < 4; p++) {
            int idx = p * 256 + tid;
            {   int row = idx >> 4, cc = (idx & 15) << 2;
                cvt_store(Kh + row * 72 + cc, Kl + row * 72 + cc, rk[p]); }
            {   int d = idx & 63, k4 = (idx >> 6) << 2;
                __nv_bfloat16 hh[4], ll[4];
                #pragma unroll
                for (int i = 0; i < 4; i++) split2(rv[p * 4 + i], hh[i], ll[i]);
                *reinterpret_cast<uint2*>(Vh + d * 72 + k4) =
                    make_uint2(pack_bf16(hh[0], hh[1]), pack_bf16(hh[2], hh[3]));
                *reinterpret_cast<uint2*>(Vl + d * 72 + k4) =
                    make_uint2(pack_bf16(ll[0], ll[1]), pack_bf16(ll[2], ll[3])); }
        }
    };

    const int r = warp * 16 + g;
    float m0 = -1e30f, m1 = -1e30f, l0 = 0.f, l1 = 0.f;
    float o[8][4];
    #pragma unroll
    for (int d8 = 0; d8 < 8; d8++)
        #pragma unroll
        for (int i = 0; i < 4; i++) o[d8][i] = 0.f;

    ldKV(0);
    stKV(0);
    __syncthreads();

    for (int j = 0; j < 16; j++) {
        const int cur = j & 1;
        if (j < 15) ldKV((j + 1) * 64);

        const __nv_bfloat16* Kh = (const __nv_bfloat16*)(smem_raw + 36864 + cur * 36864);
        const __nv_bfloat16* Kl = Kh + 64 * 72;
        const __nv_bfloat16* Vh = Kh + 2 * 64 * 72;
        const __nv_bfloat16* Vl = Kh + 3 * 64 * 72;

        float s_[8][4];
        #pragma unroll
        for (int nt = 0; nt < 8; nt++)
            #pragma unroll
            for (int i = 0; i < 4; i++) s_[nt][i] = 0.f;

        #pragma unroll
        for (int ks = 0; ks < 4; ks++) {
            const int kb = ks * 16 + (t4 << 1);
            uint32_t ah[4], al[4];
            ah[0] = *(const uint32_t*)(Qh + r * 72 + kb);
            ah[1] = *(const uint32_t*)(Qh + (r + 8) * 72 + kb);
            ah[2] = *(const uint32_t*)(Qh + r * 72 + kb + 8);
            ah[3] = *(const uint32_t*)(Qh + (r + 8) * 72 + kb + 8);
            al[0] = *(const uint32_t*)(Ql + r * 72 + kb);
            al[1] = *(const uint32_t*)(Ql + (r + 8) * 72 + kb);
            al[2] = *(const uint32_t*)(Ql + r * 72 + kb + 8);
            al[3] = *(const uint32_t*)(Ql + (r + 8) * 72 + kb + 8);
            // process 8 N-tiles in two groups of 4, term-outermost per group
            #pragma unroll
            for (int hgrp = 0; hgrp < 2; hgrp++) {
                uint32_t bh2[4][2], bl2[4][2];
                #pragma unroll
                for (int q = 0; q < 4; q++) {
                    const int n = (hgrp * 4 + q) * 8 + g;
                    bh2[q][0] = *(const uint32_t*)(Kh + n * 72 + kb);
                    bh2[q][1] = *(const uint32_t*)(Kh + n * 72 + kb + 8);
                    bl2[q][0] = *(const uint32_t*)(Kl + n * 72 + kb);
                    bl2[q][1] = *(const uint32_t*)(Kl + n * 72 + kb + 8);
                }
                #pragma unroll
                for (int q = 0; q < 4; q++) mma_bf16_16816(s_[hgrp * 4 + q], ah, bh2[q]);
                #pragma unroll
                for (int q = 0; q < 4; q++) mma_bf16_16816(s_[hgrp * 4 + q], ah, bl2[q]);
                #pragma unroll
                for (int q = 0; q < 4; q++) mma_bf16_16816(s_[hgrp * 4 + q], al, bh2[q]);
            }
        }

        float mx0 = -1e30f, mx1 = -1e30f;
        #pragma unroll
        for (int nt = 0; nt < 8; nt++) {
            mx0 = fmaxf(mx0, fmaxf(s_[nt][0], s_[nt][1]));
            mx1 = fmaxf(mx1, fmaxf(s_[nt][2], s_[nt][3]));
        }
        mx0 = fmaxf(mx0, __shfl_xor_sync(0xffffffffu, mx0, 1));
        mx0 = fmaxf(mx0, __shfl_xor_sync(0xffffffffu, mx0, 2));
        mx1 = fmaxf(mx1, __shfl_xor_sync(0xffffffffu, mx1, 1));
        mx1 = fmaxf(mx1, __shfl_xor_sync(0xffffffffu, mx1, 2));

        const float nm0 = fmaxf(m0, mx0), nm1 = fmaxf(m1, mx1);
        const float f0 = __expf(m0 - nm0), f1 = __expf(m1 - nm1);
        float sm0 = 0.f, sm1 = 0.f;
        #pragma unroll
        for (int nt = 0; nt < 8; nt++) {
            s_[nt][0] = __expf(s_[nt][0] - nm0);
            s_[nt][1] = __expf(s_[nt][1] - nm0);
            s_[nt][2] = __expf(s_[nt][2] - nm1);
            s_[nt][3] = __expf(s_[nt][3] - nm1);
            sm0 += s_[nt][0] + s_[nt][1];
            sm1 += s_[nt][2] + s_[nt][3];
        }
        sm0 += __shfl_xor_sync(0xffffffffu, sm0, 1);
        sm0 += __shfl_xor_sync(0xffffffffu, sm0, 2);
        sm1 += __shfl_xor_sync(0xffffffffu, sm1, 1);
        sm1 += __shfl_xor_sync(0xffffffffu, sm1, 2);

        l0 = l0 * f0 + sm0;  l1 = l1 * f1 + sm1;
        m0 = nm0;            m1 = nm1;

        #pragma unroll
        for (int d8 = 0; d8 < 8; d8++) {
            o[d8][0] *= f0; o[d8][1] *= f0;
            o[d8][2] *= f1; o[d8][3] *= f1;
        }

        #pragma unroll
        for (int ks = 0; ks < 4; ks++) {
            uint32_t ah[4], al[4];
            {
                __nv_bfloat16 ph[4], pl[4];
                split2(s_[2*ks][0], ph[0], pl[0]); split2(s_[2*ks][1], ph[1], pl[1]);
                split2(s_[2*ks][2], ph[2], pl[2]); split2(s_[2*ks][3], ph[3], pl[3]);
                ah[0] = pack_bf16(ph[0], ph[1]); ah[1] = pack_bf16(ph[2], ph[3]);
                al[0] = pack_bf16(pl[0], pl[1]); al[1] = pack_bf16(pl[2], pl[3]);
                split2(s_[2*ks+1][0], ph[0], pl[0]); split2(s_[2*ks+1][1], ph[1], pl[1]);
                split2(s_[2*ks+1][2], ph[2], pl[2]); split2(s_[2*ks+1][3], ph[3], pl[3]);
                ah[2] = pack_bf16(ph[0], ph[1]); ah[3] = pack_bf16(ph[2], ph[3]);
                al[2] = pack_bf16(pl[0], pl[1]); al[3] = pack_bf16(pl[2], pl[3]);
            }
            const int kb = ks * 16 + (t4 << 1);
            // 8 D-tiles in two groups of 4, term-outermost per group
            #pragma unroll
            for (int hgrp = 0; hgrp < 2; hgrp++) {
                uint32_t bh2[4][2], bl2[4][2];
                #pragma unroll
                for (int q = 0; q < 4; q++) {
                    const int n = (hgrp * 4 + q) * 8 + g;
                    bh2[q][0] = *(const uint32_t*)(Vh + n * 72 + kb);
                    bh2[q][1] = *(const uint32_t*)(Vh + n * 72 + kb + 8);
                    bl2[q][0] = *(const uint32_t*)(Vl + n * 72 + kb);
                    bl2[q][1] = *(const uint32_t*)(Vl + n * 72 + kb + 8);
                }
                #pragma unroll
                for (int q = 0; q < 4; q++) mma_bf16_16816(o[hgrp * 4 + q], ah, bh2[q]);
                #pragma unroll
                for (int q = 0; q < 4; q++) mma_bf16_16816(o[hgrp * 4 + q], ah, bl2[q]);
                #pragma unroll
                for (int q = 0; q < 4; q++) mma_bf16_16816(o[hgrp * 4 + q], al, bh2[q]);
            }
        }

        if (j < 15) stKV(cur ^ 1);
        __syncthreads();
    }

    const float i0 = 1.f / l0, i1 = 1.f / l1;
    float* O0 = att + (size_t)(b * SEQ + q0 + r) * CH + h * HDIM;
    float* O1 = O0 + (size_t)8 * CH;
    #pragma unroll
    for (int d8 = 0; d8 < 8; d8++) {
        const int c = d8 * 8 + (t4 << 1);
        *reinterpret_cast<float2*>(O0 + c) = make_float2(o[d8][0] * i0, o[d8][1] * i0);
        *reinterpret_cast<float2*>(O1 + c) = make_float2(o[d8][2] * i1, o[d8][3] * i1);
    }
}

// ---------------------------------------------------------------------------
extern "C" void kernel_launch(void* const* d_in, const int* in_sizes, int n_in,
                              void* d_out, int out_size)
{
    (void)in_sizes; (void)n_in; (void)out_size;
    const float* x     = (const float*)d_in[0];   // [8, 1024, 1024]
    const float* wqkv  = (const float*)d_in[1];   // [3072, 1024]
    const float* wproj = (const float*)d_in[2];   // [1024, 1024]
    const float* bproj = (const float*)d_in[3];   // [1024]
    float*       out   = (float*)d_out;           // [8, 1024, 1024]

    float *qkv, *att;
    cudaGetSymbolAddress((void**)&qkv, g_qkv);
    cudaGetSymbolAddress((void**)&att, g_att);

    cudaFuncSetAttribute(gemm_bf16x3<false>,
                         cudaFuncAttributeMaxDynamicSharedMemorySize, 81920);
    cudaFuncSetAttribute(gemm_bf16x3<true>,
                         cudaFuncAttributeMaxDynamicSharedMemorySize, 81920);
    cudaFuncSetAttribute(flash_attn,
                         cudaFuncAttributeMaxDynamicSharedMemorySize, 110592);

    // 1) QKV projection: [8192,1024] x [3072,1024]^T -> g_qkv [8192,3072]
    gemm_bf16x3<false><<<dim3(3 * CH / 128, M0 / 128), 256, 81920>>>(
        x, CH, wqkv, CH, qkv, 3 * CH, nullptr, CH);

    // 2) Fused flash attention -> g_att [8192,1024]
    flash_attn<<<dim3(BH, SEQ / 128), 256, 110592>>>(qkv, att);

    // 3) Output projection + bias
    gemm_bf16x3<true><<<dim3(CH / 128, M0 / 128), 256, 81920>>>(
        att, CH, wproj, CH, out, CH, bproj, CH);
}